// round 1
// baseline (speedup 1.0000x reference)
#include <cuda_runtime.h>
#include <math.h>
#include <stdint.h>

// ---------------- Problem constants ----------------
#define BATCH   4
#define SEQ     2048
#define ROWS    (BATCH*SEQ)      // 8192
#define DIMS    1024
#define STATE   2048             // 2*DIMS
#define NTOT    (4*STATE)        // 8192 columns of GEMM1 output (K|u|g_in|g_out)
#define TCH     128              // scan chunk length
#define NCH     (SEQ/TCH)        // 16 chunks

// ---------------- Scratch (device globals; no allocation allowed) ----------------
__device__ float g_xn[(size_t)ROWS*DIMS];          // 32MB  normalized input (tf32-rounded)
__device__ float g_WT[(size_t)NTOT*DIMS];          // 32MB  [Wk|Wugg]^T as [n,k]
__device__ float g_WoutT[(size_t)DIMS*STATE];      // 8MB   Wout^T as [n,k]
__device__ float g_C[(size_t)ROWS*NTOT];           // 256MB GEMM1 out: [K_sig | u_raw | gin_sig | gout_sig]
__device__ float g_out1[(size_t)ROWS*STATE];       // 64MB  h*sigmoid(g_out), tf32-rounded
__device__ float g_chA[BATCH*NCH*STATE];
__device__ float g_chB[BATCH*NCH*STATE];
__device__ float g_hin[BATCH*NCH*STATE];

// ---------------- Helpers ----------------
__device__ __forceinline__ float tf32_rna(float x) {
    uint32_t u;
    asm("cvt.rna.tf32.f32 %0, %1;" : "=r"(u) : "f"(x));
    return __uint_as_float(u);
}
__device__ __forceinline__ float sigm(float v) { return 1.0f / (1.0f + expf(-v)); }

// ---------------- RMS split norm ----------------
// xn = concat(rms(xl)*ls, rms(xr)*rs) * split_scale ; rounded to tf32
__global__ void rmsnorm_kernel(const float* __restrict__ x,
                               const float* __restrict__ ls,
                               const float* __restrict__ rs,
                               const float* __restrict__ ss,
                               float* __restrict__ xn) {
    __shared__ float wsum[8];
    int row = blockIdx.x;
    int tid = threadIdx.x;                 // 256 threads, 4 elems each
    const float* xr = x + (size_t)row * DIMS;
    float4 xv = ((const float4*)xr)[tid];
    float s = xv.x*xv.x + xv.y*xv.y + xv.z*xv.z + xv.w*xv.w;
    #pragma unroll
    for (int o = 16; o; o >>= 1) s += __shfl_xor_sync(0xffffffffu, s, o);
    if ((tid & 31) == 0) wsum[tid >> 5] = s;
    __syncthreads();
    int half = tid >> 7;                   // 0: cols 0..511, 1: cols 512..1023
    float tot = wsum[half*4+0] + wsum[half*4+1] + wsum[half*4+2] + wsum[half*4+3];
    float n = sqrtf(tot) * 0.04419417382415922f + 1e-8f;   // d^{-1/2}=1/sqrt(512)
    float inv = 1.0f / n;
    const float* sc = half ? rs : ls;
    int jb = (tid*4) & 511;
    float4 scv = ((const float4*)sc)[jb >> 2];
    float4 ssv = ((const float4*)ss)[tid];
    float4 o;
    o.x = tf32_rna(xv.x * scv.x * inv * ssv.x);
    o.y = tf32_rna(xv.y * scv.y * inv * ssv.y);
    o.z = tf32_rna(xv.z * scv.z * inv * ssv.z);
    o.w = tf32_rna(xv.w * scv.w * inv * ssv.w);
    ((float4*)(xn + (size_t)row * DIMS))[tid] = o;
}

// ---------------- Transpose (+tf32 round): dst[c*R + r] = src[r*C + c] ----------------
__global__ void transpose_rna(const float* __restrict__ src, float* __restrict__ dst,
                              int R, int C) {
    __shared__ float tile[32][33];
    int r0 = blockIdx.y * 32, c0 = blockIdx.x * 32;
    int tx = threadIdx.x, ty = threadIdx.y;   // 32 x 8
    #pragma unroll
    for (int i = 0; i < 32; i += 8)
        tile[ty+i][tx] = src[(size_t)(r0+ty+i)*C + c0 + tx];
    __syncthreads();
    #pragma unroll
    for (int i = 0; i < 32; i += 8)
        dst[(size_t)(c0+ty+i)*R + r0 + tx] = tf32_rna(tile[tx][ty+i]);
}

// ---------------- TF32 GEMM: C[M,N] = A[M,K] @ B[N,K]^T ----------------
// 128x128 CTA tile, KC=32, 8 warps in 2x4, warp tile 64x32, m16n8k8 tf32 mma.
// mode 0: GEMM1 epilogue (sigmoid on cols <2048 or >=4096, raw on u)
// mode 1: add residual (resid[M,N])
#define KC 32
#define SLD 36
__global__ void __launch_bounds__(256)
gemm_tf32(const float* __restrict__ A, const float* __restrict__ B,
          float* __restrict__ C, int M, int N, int K,
          int mode, const float* __restrict__ resid) {
    __shared__ float As[128 * SLD];
    __shared__ float Bs[128 * SLD];
    const int m0 = blockIdx.y * 128;
    const int n0 = blockIdx.x * 128;
    const int tid  = threadIdx.x;
    const int warp = tid >> 5, lane = tid & 31;
    const int g = lane >> 2, tig = lane & 3;
    const int wm0 = (warp >> 2) * 64;      // 0..1
    const int wn0 = (warp & 3) * 32;       // 0..3

    float c[4][4][4];
    #pragma unroll
    for (int i = 0; i < 4; i++)
        #pragma unroll
        for (int j = 0; j < 4; j++)
            #pragma unroll
            for (int e = 0; e < 4; e++) c[i][j][e] = 0.0f;

    const int lr  = tid >> 3;        // 0..31
    const int lc4 = (tid & 7) * 4;   // 0,4,...,28

    for (int k0 = 0; k0 < K; k0 += KC) {
        __syncthreads();
        #pragma unroll
        for (int i = 0; i < 4; i++) {
            int r = lr + i * 32;
            float4 av = *(const float4*)(A + (size_t)(m0 + r) * K + k0 + lc4);
            *(float4*)(As + r * SLD + lc4) = av;
            float4 bv = *(const float4*)(B + (size_t)(n0 + r) * K + k0 + lc4);
            *(float4*)(Bs + r * SLD + lc4) = bv;
        }
        __syncthreads();
        #pragma unroll
        for (int kk = 0; kk < KC; kk += 8) {
            uint32_t a[4][4];
            uint32_t b[4][2];
            #pragma unroll
            for (int mi = 0; mi < 4; mi++) {
                const float* p  = As + (wm0 + mi*16 + g) * SLD + kk + tig;
                const float* p2 = p + 8 * SLD;
                a[mi][0] = __float_as_uint(p[0]);
                a[mi][2] = __float_as_uint(p[4]);
                a[mi][1] = __float_as_uint(p2[0]);
                a[mi][3] = __float_as_uint(p2[4]);
            }
            #pragma unroll
            for (int ni = 0; ni < 4; ni++) {
                const float* p = Bs + (wn0 + ni*8 + g) * SLD + kk + tig;
                b[ni][0] = __float_as_uint(p[0]);
                b[ni][1] = __float_as_uint(p[4]);
            }
            #pragma unroll
            for (int mi = 0; mi < 4; mi++)
                #pragma unroll
                for (int ni = 0; ni < 4; ni++) {
                    asm volatile(
                        "mma.sync.aligned.m16n8k8.row.col.f32.tf32.tf32.f32 "
                        "{%0,%1,%2,%3},{%4,%5,%6,%7},{%8,%9},{%0,%1,%2,%3};"
                        : "+f"(c[mi][ni][0]), "+f"(c[mi][ni][1]),
                          "+f"(c[mi][ni][2]), "+f"(c[mi][ni][3])
                        : "r"(a[mi][0]), "r"(a[mi][1]), "r"(a[mi][2]), "r"(a[mi][3]),
                          "r"(b[ni][0]), "r"(b[ni][1]));
                }
        }
    }

    // Epilogue
    #pragma unroll
    for (int mi = 0; mi < 4; mi++) {
        int row = m0 + wm0 + mi*16 + g;
        #pragma unroll
        for (int ni = 0; ni < 4; ni++) {
            int col = n0 + wn0 + ni*8 + 2*tig;
            float v0 = c[mi][ni][0], v1 = c[mi][ni][1];
            float v2 = c[mi][ni][2], v3 = c[mi][ni][3];
            if (mode == 0) {
                bool sg = (col < 2048) || (col >= 4096);
                if (sg) { v0 = sigm(v0); v1 = sigm(v1); v2 = sigm(v2); v3 = sigm(v3); }
            } else {
                v0 += resid[(size_t)row * N + col];
                v1 += resid[(size_t)row * N + col + 1];
                v2 += resid[(size_t)(row+8) * N + col];
                v3 += resid[(size_t)(row+8) * N + col + 1];
            }
            *(float2*)(C + (size_t)row * N + col)     = make_float2(v0, v1);
            *(float2*)(C + (size_t)(row+8) * N + col) = make_float2(v2, v3);
        }
    }
}

// ---------------- Chunked linear-recurrence scan ----------------
// h_0 = u'_0 ; h_t = K_{t-1} * h_{t-1} + u'_t ;  u' = u * sigmoid(g_in) * (1-K)
// Phase 1: per-chunk (A = prod a, B = h with zero inflow)
__global__ void scan_phase1(const float* __restrict__ C,
                            float* __restrict__ chA, float* __restrict__ chB) {
    int cidx  = blockIdx.x * blockDim.x + threadIdx.x;   // 0..2047
    int chunk = blockIdx.y;
    int b     = blockIdx.z;
    size_t base = (size_t)b * SEQ * NTOT;
    float Aacc = 1.0f, Bacc = 0.0f;
    int t0 = chunk * TCH;
    for (int tl = 0; tl < TCH; tl++) {
        int t = t0 + tl;
        size_t r = base + (size_t)t * NTOT;
        float Kc = C[r + cidx];
        float u  = C[r + 2048 + cidx];
        float gi = C[r + 4096 + cidx];
        float a  = (t == 0) ? 1.0f : C[r - NTOT + cidx];
        float up = u * gi * (1.0f - Kc);
        Aacc = a * Aacc;
        Bacc = a * Bacc + up;
    }
    int idx = (b * NCH + chunk) * STATE + cidx;
    chA[idx] = Aacc;
    chB[idx] = Bacc;
}

// Phase 2: serial scan over NCH chunk summaries, record incoming h per chunk
__global__ void scan_phase2(const float* __restrict__ chA,
                            const float* __restrict__ chB,
                            float* __restrict__ hin) {
    int i = blockIdx.x * blockDim.x + threadIdx.x;   // 0..8191 = b*2048+c
    int b = i >> 11, cidx = i & 2047;
    float h = 0.0f;
    for (int ch = 0; ch < NCH; ch++) {
        int idx = (b * NCH + ch) * STATE + cidx;
        hin[idx] = h;
        h = chA[idx] * h + chB[idx];
    }
}

// Phase 3: replay chunk with true inflow, apply output gate, store tf32
__global__ void scan_phase3(const float* __restrict__ C,
                            const float* __restrict__ hin,
                            float* __restrict__ out1) {
    int cidx  = blockIdx.x * blockDim.x + threadIdx.x;
    int chunk = blockIdx.y;
    int b     = blockIdx.z;
    size_t base = (size_t)b * SEQ * NTOT;
    float h = hin[(b * NCH + chunk) * STATE + cidx];
    int t0 = chunk * TCH;
    for (int tl = 0; tl < TCH; tl++) {
        int t = t0 + tl;
        size_t r = base + (size_t)t * NTOT;
        float Kc = C[r + cidx];
        float u  = C[r + 2048 + cidx];
        float gi = C[r + 4096 + cidx];
        float go = C[r + 6144 + cidx];
        float a  = (t == 0) ? 1.0f : C[r - NTOT + cidx];
        float up = u * gi * (1.0f - Kc);
        h = a * h + up;
        out1[((size_t)b * SEQ + t) * STATE + cidx] = tf32_rna(h * go);
    }
}

// ---------------- Launch ----------------
extern "C" void kernel_launch(void* const* d_in, const int* in_sizes, int n_in,
                              void* d_out, int out_size) {
    const float* x    = (const float*)d_in[0];
    const float* ls   = (const float*)d_in[1];
    const float* rs   = (const float*)d_in[2];
    const float* ss   = (const float*)d_in[3];
    const float* Wk   = (const float*)d_in[4];
    const float* Wugg = (const float*)d_in[5];
    const float* Wout = (const float*)d_in[6];
    float* y = (float*)d_out;

    float *p_xn, *p_WT, *p_WoutT, *p_C, *p_out1, *p_chA, *p_chB, *p_hin;
    cudaGetSymbolAddress((void**)&p_xn,    g_xn);
    cudaGetSymbolAddress((void**)&p_WT,    g_WT);
    cudaGetSymbolAddress((void**)&p_WoutT, g_WoutT);
    cudaGetSymbolAddress((void**)&p_C,     g_C);
    cudaGetSymbolAddress((void**)&p_out1,  g_out1);
    cudaGetSymbolAddress((void**)&p_chA,   g_chA);
    cudaGetSymbolAddress((void**)&p_chB,   g_chB);
    cudaGetSymbolAddress((void**)&p_hin,   g_hin);

    // 1) RMS split norm
    rmsnorm_kernel<<<ROWS, 256>>>(x, ls, rs, ss, p_xn);

    // 2) Transposed+rounded weights: WT rows [0,2048)=Wk^T, [2048,8192)=Wugg^T
    {
        dim3 blk(32, 8);
        transpose_rna<<<dim3(2048/32, 1024/32), blk>>>(Wk,   p_WT,                 1024, 2048);
        transpose_rna<<<dim3(6144/32, 1024/32), blk>>>(Wugg, p_WT + (size_t)2048*1024, 1024, 6144);
        transpose_rna<<<dim3(1024/32, 2048/32), blk>>>(Wout, p_WoutT,              2048, 1024);
    }

    // 3) GEMM1: C[8192,8192] = xn @ [Wk|Wugg], fused sigmoids
    gemm_tf32<<<dim3(NTOT/128, ROWS/128), 256>>>(p_xn, p_WT, p_C,
                                                 ROWS, NTOT, DIMS, 0, nullptr);

    // 4) Scan
    scan_phase1<<<dim3(STATE/256, NCH, BATCH), 256>>>(p_C, p_chA, p_chB);
    scan_phase2<<<(BATCH*STATE)/256, 256>>>(p_chA, p_chB, p_hin);
    scan_phase3<<<dim3(STATE/256, NCH, BATCH), 256>>>(p_C, p_hin, p_out1);

    // 5) GEMM2: y = outputs @ Wout + x
    gemm_tf32<<<dim3(DIMS/128, ROWS/128), 256>>>(p_out1, p_WoutT, y,
                                                 ROWS, DIMS, STATE, 1, x);
}

// round 3
// speedup vs baseline: 1.9940x; 1.9940x over previous
#include <cuda_runtime.h>
#include <cuda_bf16.h>
#include <math.h>
#include <stdint.h>

// ---------------- Problem constants ----------------
#define BATCH   4
#define SEQ     2048
#define ROWS    (BATCH*SEQ)      // 8192
#define DIMS    1024
#define STATE   2048             // 2*DIMS
#define NTOT    (4*STATE)        // 8192 columns of GEMM1 output (K|u|g_in|g_out)
#define TCH     128              // scan chunk length
#define NCH     (SEQ/TCH)        // 16 chunks

// ---------------- Scratch (device globals; no allocation allowed) ----------------
__device__ __nv_bfloat16 g_xn[(size_t)ROWS*DIMS];       // 16MB  normalized input (bf16)
__device__ __nv_bfloat16 g_WT[(size_t)NTOT*DIMS];       // 16MB  [Wk|Wugg]^T as [n,k] bf16
__device__ __nv_bfloat16 g_WoutT[(size_t)DIMS*STATE];   // 4MB   Wout^T as [n,k] bf16
__device__ float g_C[(size_t)ROWS*NTOT];                // 256MB GEMM1 out (sig(K)|u|sig(gin)|sig(gout))
__device__ __nv_bfloat16 g_out1[(size_t)ROWS*STATE];    // 32MB  h*sigmoid(g_out) bf16
__device__ float g_chA[BATCH*NCH*STATE];
__device__ float g_chB[BATCH*NCH*STATE];
__device__ float g_hin[BATCH*NCH*STATE];

// ---------------- Helpers ----------------
__device__ __forceinline__ uint32_t smem_u32(const void* p) {
    uint32_t a;
    asm("{ .reg .u64 t; cvta.to.shared.u64 t, %1; cvt.u32.u64 %0, t; }" : "=r"(a) : "l"(p));
    return a;
}
__device__ __forceinline__ void cp16(uint32_t dst, const void* src) {
    asm volatile("cp.async.cg.shared.global [%0], [%1], 16;" :: "r"(dst), "l"(src) : "memory");
}
#define CP_COMMIT() asm volatile("cp.async.commit_group;" ::: "memory")

__device__ __forceinline__ void ldm_x4(uint32_t* r, uint32_t addr) {
    asm volatile("ldmatrix.sync.aligned.m8n8.x4.shared.b16 {%0,%1,%2,%3}, [%4];"
                 : "=r"(r[0]), "=r"(r[1]), "=r"(r[2]), "=r"(r[3]) : "r"(addr));
}
__device__ __forceinline__ void mma_bf16(float* c, const uint32_t* a,
                                         uint32_t b0, uint32_t b1) {
    asm volatile(
        "mma.sync.aligned.m16n8k16.row.col.f32.bf16.bf16.f32 "
        "{%0,%1,%2,%3},{%4,%5,%6,%7},{%8,%9},{%0,%1,%2,%3};"
        : "+f"(c[0]), "+f"(c[1]), "+f"(c[2]), "+f"(c[3])
        : "r"(a[0]), "r"(a[1]), "r"(a[2]), "r"(a[3]), "r"(b0), "r"(b1));
}
__device__ __forceinline__ float sigm(float v) { return 1.0f / (1.0f + expf(-v)); }

// ---------------- RMS split norm -> bf16 ----------------
__global__ void rmsnorm_kernel(const float* __restrict__ x,
                               const float* __restrict__ ls,
                               const float* __restrict__ rs,
                               const float* __restrict__ ss,
                               __nv_bfloat16* __restrict__ xn) {
    __shared__ float wsum[8];
    int row = blockIdx.x;
    int tid = threadIdx.x;                 // 256 threads, 4 elems each
    const float* xr = x + (size_t)row * DIMS;
    float4 xv = ((const float4*)xr)[tid];
    float s = xv.x*xv.x + xv.y*xv.y + xv.z*xv.z + xv.w*xv.w;
    #pragma unroll
    for (int o = 16; o; o >>= 1) s += __shfl_xor_sync(0xffffffffu, s, o);
    if ((tid & 31) == 0) wsum[tid >> 5] = s;
    __syncthreads();
    int half = tid >> 7;
    float tot = wsum[half*4+0] + wsum[half*4+1] + wsum[half*4+2] + wsum[half*4+3];
    float n = sqrtf(tot) * 0.04419417382415922f + 1e-8f;   // 1/sqrt(512)
    float inv = 1.0f / n;
    const float* sc = half ? rs : ls;
    int jb = (tid*4) & 511;
    float4 scv = ((const float4*)sc)[jb >> 2];
    float4 ssv = ((const float4*)ss)[tid];
    __nv_bfloat162 p0 = __floats2bfloat162_rn(xv.x * scv.x * inv * ssv.x,
                                              xv.y * scv.y * inv * ssv.y);
    __nv_bfloat162 p1 = __floats2bfloat162_rn(xv.z * scv.z * inv * ssv.z,
                                              xv.w * scv.w * inv * ssv.w);
    __nv_bfloat162* dst = (__nv_bfloat162*)(xn + (size_t)row * DIMS);
    dst[tid*2]   = p0;
    dst[tid*2+1] = p1;
}

// ---------------- Transpose fp32 -> bf16: dst[c*R + r] = src[r*C + c] ----------------
__global__ void transpose_bf16(const float* __restrict__ src, __nv_bfloat16* __restrict__ dst,
                               int R, int C) {
    __shared__ float tile[32][33];
    int r0 = blockIdx.y * 32, c0 = blockIdx.x * 32;
    int tx = threadIdx.x, ty = threadIdx.y;   // 32 x 8
    #pragma unroll
    for (int i = 0; i < 32; i += 8)
        tile[ty+i][tx] = src[(size_t)(r0+ty+i)*C + c0 + tx];
    __syncthreads();
    #pragma unroll
    for (int i = 0; i < 32; i += 8)
        dst[(size_t)(c0+ty+i)*R + r0 + tx] = __float2bfloat16_rn(tile[tx][ty+i]);
}

// ---------------- Legacy-MMA bf16 GEMM: C[M,N] = A[M,K] @ B[N,K]^T ----------------
// CTA tile 128x128, BK=64, 3-stage cp.async pipeline, 256 threads (8 warps 2x4),
// warp tile 64x32, ldmatrix.x4 + m16n8k16 bf16 mma, 2 CTAs/SM.
// mode 0: GEMM1 epilogue (sigmoid on cols <2048 or >=4096)
// mode 1: add residual (resid[M,N])
#define BK 64
#define NST 3
#define AST (128*BK*2)         // 16384 bytes per A stage (128 rows x 128B)
#define BST (128*BK*2)         // 16384 bytes per B stage
#define GEMM_SMEM (NST*(AST+BST))   // 98304 = 96KB

__device__ __forceinline__ void fill_tiles(uint32_t aS, uint32_t bS,
        const __nv_bfloat16* __restrict__ A, const __nv_bfloat16* __restrict__ B,
        int m0, int n0, int K, int k0, int tid) {
    #pragma unroll
    for (int i = 0; i < 4; i++) {              // A: 128 rows x 8 16B-chunks
        int idx = tid + i*256;
        int r = idx >> 3, c = idx & 7;
        cp16(aS + r*128 + ((c ^ (r & 7)) << 4),
             A + (size_t)(m0 + r)*K + k0 + c*8);
    }
    #pragma unroll
    for (int i = 0; i < 4; i++) {              // B: 128 rows x 8 16B-chunks
        int idx = tid + i*256;
        int r = idx >> 3, c = idx & 7;
        cp16(bS + r*128 + ((c ^ (r & 7)) << 4),
             B + (size_t)(n0 + r)*K + k0 + c*8);
    }
    CP_COMMIT();
}

__global__ void __launch_bounds__(256, 2)
gemm_bf16(const __nv_bfloat16* __restrict__ A, const __nv_bfloat16* __restrict__ B,
          float* __restrict__ Cout, int N, int K, int NIT,
          int mode, const float* __restrict__ resid) {
    extern __shared__ char smraw[];
    const uint32_t sbase = smem_u32(smraw);

    const int tid  = threadIdx.x;
    const int wid  = tid >> 5;
    const int lane = tid & 31;
    const int m0 = blockIdx.y * 128;
    const int n0 = blockIdx.x * 128;
    const int wm0 = (wid >> 2) * 64;      // warp row origin (0/64)
    const int wn0 = (wid & 3) * 32;       // warp col origin (0/32/64/96)
    const int blk = lane >> 3;            // 0..3 (8x8 block id in ldmatrix)
    const int lr8 = lane & 7;
    const int kb2 = (blk >> 1) * 16;      // +16B for k8..15 half

    // per-warp ldmatrix row offsets (swizzle-decomposed)
    uint32_t offA[4], xrA[4], offB[2], xrB[2];
    #pragma unroll
    for (int mt = 0; mt < 4; mt++) {
        int r = wm0 + mt*16 + (blk & 1)*8 + lr8;
        offA[mt] = (uint32_t)r * 128u;
        xrA[mt]  = (uint32_t)(r & 7) << 4;
    }
    #pragma unroll
    for (int np = 0; np < 2; np++) {
        int r = wn0 + np*16 + (blk & 1)*8 + lr8;
        offB[np] = (uint32_t)r * 128u;
        xrB[np]  = (uint32_t)(r & 7) << 4;
    }

    float c[4][4][4];
    #pragma unroll
    for (int i = 0; i < 4; i++)
        #pragma unroll
        for (int j = 0; j < 4; j++)
            #pragma unroll
            for (int e = 0; e < 4; e++) c[i][j][e] = 0.0f;

    // Prologue: fill all 3 stages
    #pragma unroll
    for (int pf = 0; pf < NST; ++pf)
        fill_tiles(sbase + pf*(AST+BST), sbase + pf*(AST+BST) + AST,
                   A, B, m0, n0, K, pf*BK, tid);

    for (int it = 0; it < NIT; ++it) {
        const int s = it % NST;
        const uint32_t aS = sbase + s*(AST+BST);
        const uint32_t bS = aS + AST;

        // wait for this stage's fill (keep up to 2 newer groups in flight)
        int rem = NIT - 1 - it;
        if (rem >= 2)      asm volatile("cp.async.wait_group 2;" ::: "memory");
        else if (rem == 1) asm volatile("cp.async.wait_group 1;" ::: "memory");
        else               asm volatile("cp.async.wait_group 0;" ::: "memory");
        __syncthreads();

        #pragma unroll
        for (int kk = 0; kk < 4; ++kk) {
            uint32_t a[4][4], b[2][4];
            const uint32_t kbase = (uint32_t)(kk*32) + kb2;
            #pragma unroll
            for (int mt = 0; mt < 4; mt++)
                ldm_x4(a[mt], aS + offA[mt] + (kbase ^ xrA[mt]));
            #pragma unroll
            for (int np = 0; np < 2; np++)
                ldm_x4(b[np], bS + offB[np] + (kbase ^ xrB[np]));
            #pragma unroll
            for (int mt = 0; mt < 4; mt++)
                #pragma unroll
                for (int nt = 0; nt < 4; nt++) {
                    int np = nt >> 1, odd = nt & 1;
                    mma_bf16(c[mt][nt], a[mt], b[np][odd], b[np][2 + odd]);
                }
        }
        __syncthreads();   // everyone done reading stage s

        if (it + 3 < NIT)
            fill_tiles(aS, bS, A, B, m0, n0, K, (it + 3)*BK, tid);
    }

    // Epilogue: direct float2 stores (32B sectors fully covered by 4-lane groups)
    const int g = lane >> 2, tig = lane & 3;
    #pragma unroll
    for (int mt = 0; mt < 4; mt++) {
        int row = m0 + wm0 + mt*16 + g;
        #pragma unroll
        for (int nt = 0; nt < 4; nt++) {
            int col = n0 + wn0 + nt*8 + 2*tig;
            float v0 = c[mt][nt][0], v1 = c[mt][nt][1];
            float v2 = c[mt][nt][2], v3 = c[mt][nt][3];
            if (mode == 0) {
                bool sg = (col < 2048) || (col >= 4096);
                if (sg) { v0 = sigm(v0); v1 = sigm(v1); v2 = sigm(v2); v3 = sigm(v3); }
            } else {
                v0 += resid[(size_t)row * N + col];
                v1 += resid[(size_t)row * N + col + 1];
                v2 += resid[(size_t)(row+8) * N + col];
                v3 += resid[(size_t)(row+8) * N + col + 1];
            }
            *(float2*)(Cout + (size_t)row * N + col)     = make_float2(v0, v1);
            *(float2*)(Cout + (size_t)(row+8) * N + col) = make_float2(v2, v3);
        }
    }
}

// ---------------- Chunked linear-recurrence scan ----------------
__global__ void scan_phase1(const float* __restrict__ C,
                            float* __restrict__ chA, float* __restrict__ chB) {
    int cidx  = blockIdx.x * blockDim.x + threadIdx.x;   // 0..2047
    int chunk = blockIdx.y;
    int b     = blockIdx.z;
    size_t base = (size_t)b * SEQ * NTOT;
    float Aacc = 1.0f, Bacc = 0.0f;
    int t0 = chunk * TCH;
    for (int tl = 0; tl < TCH; tl++) {
        int t = t0 + tl;
        size_t r = base + (size_t)t * NTOT;
        float Kc = C[r + cidx];
        float u  = C[r + 2048 + cidx];
        float gi = C[r + 4096 + cidx];
        float a  = (t == 0) ? 1.0f : C[r - NTOT + cidx];
        float up = u * gi * (1.0f - Kc);
        Aacc = a * Aacc;
        Bacc = a * Bacc + up;
    }
    int idx = (b * NCH + chunk) * STATE + cidx;
    chA[idx] = Aacc;
    chB[idx] = Bacc;
}

__global__ void scan_phase2(const float* __restrict__ chA,
                            const float* __restrict__ chB,
                            float* __restrict__ hin) {
    int i = blockIdx.x * blockDim.x + threadIdx.x;   // b*2048+c
    int b = i >> 11, cidx = i & 2047;
    float h = 0.0f;
    for (int ch = 0; ch < NCH; ch++) {
        int idx = (b * NCH + ch) * STATE + cidx;
        hin[idx] = h;
        h = chA[idx] * h + chB[idx];
    }
}

__global__ void scan_phase3(const float* __restrict__ C,
                            const float* __restrict__ hin,
                            __nv_bfloat16* __restrict__ out1) {
    int cidx  = blockIdx.x * blockDim.x + threadIdx.x;
    int chunk = blockIdx.y;
    int b     = blockIdx.z;
    size_t base = (size_t)b * SEQ * NTOT;
    float h = hin[(b * NCH + chunk) * STATE + cidx];
    int t0 = chunk * TCH;
    for (int tl = 0; tl < TCH; tl++) {
        int t = t0 + tl;
        size_t r = base + (size_t)t * NTOT;
        float Kc = C[r + cidx];
        float u  = C[r + 2048 + cidx];
        float gi = C[r + 4096 + cidx];
        float go = C[r + 6144 + cidx];
        float a  = (t == 0) ? 1.0f : C[r - NTOT + cidx];
        float up = u * gi * (1.0f - Kc);
        h = a * h + up;
        out1[((size_t)b * SEQ + t) * STATE + cidx] = __float2bfloat16_rn(h * go);
    }
}

// ---------------- Launch ----------------
extern "C" void kernel_launch(void* const* d_in, const int* in_sizes, int n_in,
                              void* d_out, int out_size) {
    const float* x    = (const float*)d_in[0];
    const float* ls   = (const float*)d_in[1];
    const float* rs   = (const float*)d_in[2];
    const float* ss   = (const float*)d_in[3];
    const float* Wk   = (const float*)d_in[4];
    const float* Wugg = (const float*)d_in[5];
    const float* Wout = (const float*)d_in[6];
    float* y = (float*)d_out;

    __nv_bfloat16 *p_xn, *p_WT, *p_WoutT, *p_out1;
    float *p_C, *p_chA, *p_chB, *p_hin;
    cudaGetSymbolAddress((void**)&p_xn,    g_xn);
    cudaGetSymbolAddress((void**)&p_WT,    g_WT);
    cudaGetSymbolAddress((void**)&p_WoutT, g_WoutT);
    cudaGetSymbolAddress((void**)&p_C,     g_C);
    cudaGetSymbolAddress((void**)&p_out1,  g_out1);
    cudaGetSymbolAddress((void**)&p_chA,   g_chA);
    cudaGetSymbolAddress((void**)&p_chB,   g_chB);
    cudaGetSymbolAddress((void**)&p_hin,   g_hin);

    cudaFuncSetAttribute(gemm_bf16, cudaFuncAttributeMaxDynamicSharedMemorySize, GEMM_SMEM);

    // 1) RMS split norm -> bf16
    rmsnorm_kernel<<<ROWS, 256>>>(x, ls, rs, ss, p_xn);

    // 2) Transposed bf16 weights
    {
        dim3 blk(32, 8);
        transpose_bf16<<<dim3(2048/32, 1024/32), blk>>>(Wk,   p_WT,                      1024, 2048);
        transpose_bf16<<<dim3(6144/32, 1024/32), blk>>>(Wugg, p_WT + (size_t)2048*1024,  1024, 6144);
        transpose_bf16<<<dim3(1024/32, 2048/32), blk>>>(Wout, p_WoutT,                   2048, 1024);
    }

    // 3) GEMM1: C[8192,8192] = xn @ [Wk|Wugg], fused sigmoids
    gemm_bf16<<<dim3(NTOT/128, ROWS/128), 256, GEMM_SMEM>>>(p_xn, p_WT, p_C,
                                                            NTOT, DIMS, DIMS/BK, 0, nullptr);

    // 4) Scan
    scan_phase1<<<dim3(STATE/256, NCH, BATCH), 256>>>(p_C, p_chA, p_chB);
    scan_phase2<<<(BATCH*STATE)/256, 256>>>(p_chA, p_chB, p_hin);
    scan_phase3<<<dim3(STATE/256, NCH, BATCH), 256>>>(p_C, p_hin, p_out1);

    // 5) GEMM2: y = outputs @ Wout + x
    gemm_bf16<<<dim3(DIMS/128, ROWS/128), 256, GEMM_SMEM>>>(p_out1, p_WoutT, y,
                                                            DIMS, STATE, STATE/BK, 1, x);
}